// round 11
// baseline (speedup 1.0000x reference)
#include <cuda_runtime.h>
#include <cuda_fp16.h>
#include <cstdint>
#include <cstddef>

#define BB 4096
#define HH 2048
#define VV 32000
#define TM 128
#define TN 128
#define TK 64
#define NKT (HH/TK)        // 32 k-stages
#define NTILES (VV/TN)     // 250 v-tiles
#define NVC 9              // v-chunks (grid.y)
#define IGNORE_INDEX (-100)

// ---- device scratch (no allocations allowed) ----
__device__ __half g_xb[(size_t)BB*HH];
__device__ __half g_wb[(size_t)VV*HH];
__device__ float g_S[NVC*BB];
__device__ float g_T[NVC*BB];
__device__ float g_L[BB/2];

// SW128 swizzle on byte offset within a [rows][128B] tile: chunk ^= (row&7)
#define SWZ(b) ((b) ^ (((b) >> 3) & 0x70))

// ============================ convert fp32 -> fp16 ============================
__global__ void convert_fp16_kernel(const float* __restrict__ x,
                                    const float* __restrict__ W) {
    size_t i = (size_t)blockIdx.x * blockDim.x + threadIdx.x;
    const size_t n1 = (size_t)BB * HH / 4;
    const size_t n2 = (size_t)VV * HH / 4;
    if (i < n1) {
        float4 v = reinterpret_cast<const float4*>(x)[i];
        __half2* o = reinterpret_cast<__half2*>(g_xb);
        o[2*i]   = __floats2half2_rn(v.x, v.y);
        o[2*i+1] = __floats2half2_rn(v.z, v.w);
    } else if (i < n1 + n2) {
        size_t j = i - n1;
        float4 v = reinterpret_cast<const float4*>(W)[j];
        __half2* o = reinterpret_cast<__half2*>(g_wb);
        o[2*j]   = __floats2half2_rn(v.x, v.y);
        o[2*j+1] = __floats2half2_rn(v.z, v.w);
    }
}

// ============== exact fp32 gather of logit[y_r] (one warp per row) ===========
// y is INT32 (JAX x64-disabled: randint(dtype=int64) silently yields int32).
__global__ void gather_target_kernel(const float* __restrict__ x,
                                     const float* __restrict__ W,
                                     const int* __restrict__ y) {
    int r = blockIdx.x * 8 + (threadIdx.x >> 5);
    int l = threadIdx.x & 31;
    if (r >= BB/2) return;
    int yy = y[r];
    if (yy == IGNORE_INDEX || yy < 0 || yy >= VV) { if (l == 0) g_L[r] = 0.f; return; }
    const float4* xr = reinterpret_cast<const float4*>(x + (size_t)r * HH);
    const float4* wr = reinterpret_cast<const float4*>(W + (size_t)yy * HH);
    float s = 0.f;
    #pragma unroll 4
    for (int i = l; i < HH/4; i += 32) {
        float4 a = xr[i], b = wr[i];
        s += a.x*b.x + a.y*b.y + a.z*b.z + a.w*b.w;
    }
    #pragma unroll
    for (int o = 16; o; o >>= 1) s += __shfl_xor_sync(0xffffffffu, s, o);
    if (l == 0) g_L[r] = s;
}

// ============================ fused GEMM + reductions ========================
__global__ void __launch_bounds__(256, 2)
orpo_gemm_kernel() {
    extern __shared__ unsigned char smem_raw[];
    unsigned char* Asm = smem_raw;                 // 2 stages * 16384 B
    unsigned char* Bsm = smem_raw + 2 * 16384;     // 2 stages * 16384 B
    __shared__ float Ssh[2][TM];
    __shared__ float Tsh[2][TM];

    const int tid = threadIdx.x;
    const int l   = tid & 31;
    const int wid = tid >> 5;
    const int wm  = wid & 3;       // 4 warps in M (32 rows each)
    const int wn  = wid >> 2;      // 2 warps in N (64 cols each)
    const int rowBase = blockIdx.x * TM;

    if (tid < TM) {
        Ssh[0][tid] = 0.f; Ssh[1][tid] = 0.f;
        Tsh[0][tid] = 0.f; Tsh[1][tid] = 0.f;
    }
    __syncthreads();

    const uint32_t aBase = (uint32_t)__cvta_generic_to_shared(Asm);
    const uint32_t bBase = (uint32_t)__cvta_generic_to_shared(Bsm);

    // cp.async addressing: thread covers (r0 + it*32, ch) for it=0..3
    const int r0 = tid >> 3;
    const int ch = tid & 7;
    const uint32_t dOff0 = SWZ((uint32_t)(r0 * 128 + ch * 16)); // + it*4096 (r&7 invariant)
    const __half* gaP = g_xb + (size_t)(rowBase + r0) * HH + ch * 8;

    // ldmatrix per-lane constants
    const uint32_t aColB = (uint32_t)((l >> 4) << 4);        // A k-offset bytes
    const uint32_t bColB = (uint32_t)(((l >> 3) & 1) << 4);  // B k-offset bytes

    float acc[2][8][4];

    for (int t = blockIdx.y; t < NTILES; t += NVC) {
        #pragma unroll
        for (int mt = 0; mt < 2; ++mt)
            #pragma unroll
            for (int nt = 0; nt < 8; ++nt)
                #pragma unroll
                for (int e = 0; e < 4; ++e) acc[mt][nt][e] = 0.f;

        const __half* gbP = g_wb + (size_t)(t * TN + r0) * HH + ch * 8;

        // prologue: stage 0
        #pragma unroll
        for (int it = 0; it < 4; ++it) {
            uint32_t da = aBase + dOff0 + it * 4096;
            const void* ga = gaP + (size_t)it * 32 * HH;
            asm volatile("cp.async.cg.shared.global [%0], [%1], 16;\n" :: "r"(da), "l"(ga));
            uint32_t db = bBase + dOff0 + it * 4096;
            const void* gb = gbP + (size_t)it * 32 * HH;
            asm volatile("cp.async.cg.shared.global [%0], [%1], 16;\n" :: "r"(db), "l"(gb));
        }
        asm volatile("cp.async.commit_group;\n" ::: "memory");

        for (int kt = 0; kt < NKT; ++kt) {
            const int cur = kt & 1;
            if (kt + 1 < NKT) {
                const int s = cur ^ 1;
                const int kof = (kt + 1) * TK;   // elements
                #pragma unroll
                for (int it = 0; it < 4; ++it) {
                    uint32_t da = aBase + s * 16384 + dOff0 + it * 4096;
                    const void* ga = gaP + (size_t)it * 32 * HH + kof;
                    asm volatile("cp.async.cg.shared.global [%0], [%1], 16;\n" :: "r"(da), "l"(ga));
                    uint32_t db = bBase + s * 16384 + dOff0 + it * 4096;
                    const void* gb = gbP + (size_t)it * 32 * HH + kof;
                    asm volatile("cp.async.cg.shared.global [%0], [%1], 16;\n" :: "r"(db), "l"(gb));
                }
                asm volatile("cp.async.commit_group;\n" ::: "memory");
                asm volatile("cp.async.wait_group 1;\n" ::: "memory");
            } else {
                asm volatile("cp.async.wait_group 0;\n" ::: "memory");
            }
            __syncthreads();

            const uint32_t aS = aBase + cur * 16384;
            const uint32_t bS = bBase + cur * 16384;
            #pragma unroll
            for (int kk = 0; kk < 4; ++kk) {   // 4 x k16 per stage
                uint32_t af[2][4];
                #pragma unroll
                for (int mt = 0; mt < 2; ++mt) {
                    uint32_t off = (uint32_t)((wm * 32 + mt * 16 + (l & 15)) * 128 + kk * 32) + aColB;
                    uint32_t ad = aS + SWZ(off);
                    asm volatile("ldmatrix.sync.aligned.m8n8.x4.shared.b16 {%0,%1,%2,%3}, [%4];\n"
                        : "=r"(af[mt][0]), "=r"(af[mt][1]), "=r"(af[mt][2]), "=r"(af[mt][3])
                        : "r"(ad));
                }
                uint32_t bf[8][2];
                #pragma unroll
                for (int np = 0; np < 4; ++np) {
                    uint32_t off = (uint32_t)((wn * 64 + np * 16 + ((l >> 4) << 3) + (l & 7)) * 128 + kk * 32) + bColB;
                    uint32_t bd = bS + SWZ(off);
                    asm volatile("ldmatrix.sync.aligned.m8n8.x4.shared.b16 {%0,%1,%2,%3}, [%4];\n"
                        : "=r"(bf[2*np][0]), "=r"(bf[2*np][1]), "=r"(bf[2*np+1][0]), "=r"(bf[2*np+1][1])
                        : "r"(bd));
                }
                #pragma unroll
                for (int mt = 0; mt < 2; ++mt)
                    #pragma unroll
                    for (int nt = 0; nt < 8; ++nt) {
                        asm volatile(
                            "mma.sync.aligned.m16n8k16.row.col.f32.f16.f16.f32 "
                            "{%0,%1,%2,%3}, {%4,%5,%6,%7}, {%8,%9}, {%0,%1,%2,%3};\n"
                            : "+f"(acc[mt][nt][0]), "+f"(acc[mt][nt][1]),
                              "+f"(acc[mt][nt][2]), "+f"(acc[mt][nt][3])
                            : "r"(af[mt][0]), "r"(af[mt][1]), "r"(af[mt][2]), "r"(af[mt][3]),
                              "r"(bf[nt][0]), "r"(bf[nt][1]));
                    }
            }
            __syncthreads();
        }

        // ---- epilogue: online reductions (no logits stored) ----
        float sE[4] = {0.f, 0.f, 0.f, 0.f};
        float sTt[4] = {0.f, 0.f, 0.f, 0.f};
        #pragma unroll
        for (int mt = 0; mt < 2; ++mt)
            #pragma unroll
            for (int nt = 0; nt < 8; ++nt)
                #pragma unroll
                for (int e = 0; e < 4; ++e) {
                    float v = acc[mt][nt][e];
                    int rp = mt * 2 + (e >> 1);
                    sE[rp]  += __expf(v);
                    sTt[rp] += v;
                }
        #pragma unroll
        for (int ofs = 1; ofs <= 2; ofs <<= 1)
            #pragma unroll
            for (int rp = 0; rp < 4; ++rp) {
                sE[rp]  += __shfl_xor_sync(0xffffffffu, sE[rp], ofs);
                sTt[rp] += __shfl_xor_sync(0xffffffffu, sTt[rp], ofs);
            }
        if ((l & 3) == 0) {
            #pragma unroll
            for (int rp = 0; rp < 4; ++rp) {
                int rl = wm * 32 + (rp >> 1) * 16 + ((rp & 1) << 3) + (l >> 2);
                Ssh[wn][rl] += sE[rp];     // unique (wn,rl) writer -> no atomics
                Tsh[wn][rl] += sTt[rp];
            }
        }
    }

    __syncthreads();
    if (tid < TM) {
        g_S[blockIdx.y * BB + rowBase + tid] = Ssh[0][tid] + Ssh[1][tid];
        g_T[blockIdx.y * BB + rowBase + tid] = Tsh[0][tid] + Tsh[1][tid];
    }
}

// ============================ finalize (double) ==============================
__global__ void orpo_finalize_kernel(const int* __restrict__ y,
                                     float* __restrict__ out) {
    __shared__ double msh[BB];
    __shared__ double red[256];
    const int tid = threadIdx.x;

    double pnll = 0.0, pcnt = 0.0;
    for (int r = tid; r < BB; r += 256) {
        double S = 0.0, T = 0.0;
        #pragma unroll
        for (int c = 0; c < NVC; ++c) { S += (double)g_S[c*BB + r]; T += (double)g_T[c*BB + r]; }
        double lz = log(S);
        msh[r] = T / (double)VV - lz;            // mean log-prob of row r
        if (r < BB/2) {
            if (y[r] != IGNORE_INDEX) { pnll += lz - (double)g_L[r]; pcnt += 1.0; }
        }
    }
    __syncthreads();

    double por = 0.0;
    for (int r = tid; r < BB/2; r += 256) {
        double chs = msh[r], rj = msh[r + BB/2];
        double lo = (chs - rj) - (log1p(-exp(chs)) - log1p(-exp(rj)));
        double ls = (lo > 0.0) ? -log1p(exp(-lo)) : lo - log1p(exp(lo));
        por += 0.1 * ls;                         // BETA * log_sigmoid(log_odds)
    }

    red[tid] = pnll; __syncthreads();
    for (int s = 128; s > 0; s >>= 1) { if (tid < s) red[tid] += red[tid + s]; __syncthreads(); }
    double nll_sum = red[0]; __syncthreads();
    red[tid] = pcnt; __syncthreads();
    for (int s = 128; s > 0; s >>= 1) { if (tid < s) red[tid] += red[tid + s]; __syncthreads(); }
    double cnt = red[0]; __syncthreads();
    red[tid] = por; __syncthreads();
    for (int s = 128; s > 0; s >>= 1) { if (tid < s) red[tid] += red[tid + s]; __syncthreads(); }

    if (tid == 0) {
        double denom = (cnt > 1.0) ? cnt : 1.0;
        out[0] = (float)(nll_sum / denom - red[0] / (double)(BB/2));
    }
}

// ============================ launch =========================================
extern "C" void kernel_launch(void* const* d_in, const int* in_sizes, int n_in,
                              void* d_out, int out_size) {
    const float* x = (const float*)d_in[0];
    const float* W = (const float*)d_in[1];
    const int* y = (const int*)d_in[2];     // int32 labels
    float* out = (float*)d_out;

    const size_t nvec = ((size_t)BB*HH + (size_t)VV*HH) / 4;
    convert_fp16_kernel<<<(int)((nvec + 255) / 256), 256>>>(x, W);

    gather_target_kernel<<<(BB/2 + 7) / 8, 256>>>(x, W, y);

    cudaFuncSetAttribute(orpo_gemm_kernel,
                         cudaFuncAttributeMaxDynamicSharedMemorySize, 65536);
    dim3 grid(BB / TM, NVC);
    orpo_gemm_kernel<<<grid, 256, 65536>>>();

    orpo_finalize_kernel<<<1, 256>>>(y, out);
}

// round 13
// speedup vs baseline: 1.1266x; 1.1266x over previous
#include <cuda_runtime.h>
#include <cuda_fp16.h>
#include <cstdint>
#include <cstddef>

#define BB 4096
#define HH 2048
#define VV 32000
#define TM 128
#define TN 128
#define TK 64
#define NKT (HH/TK)        // 32 k-stages
#define NTILES (VV/TN)     // 250 v-tiles
#define NVC 9              // v-chunks (grid.y)
#define IGNORE_INDEX (-100)
#define FIN_BLOCKS 8

// ---- device scratch (no allocations allowed) ----
__device__ __half g_xb[(size_t)BB*HH];
__device__ __half g_wb[(size_t)VV*HH];
__device__ float g_S[NVC*BB];
__device__ float g_T[NVC*BB];
__device__ float g_L[BB/2];
__device__ double g_pnll[FIN_BLOCKS];
__device__ double g_pcnt[FIN_BLOCKS];
__device__ double g_por[FIN_BLOCKS];

// SW128 swizzle on byte offset within a [rows][128B] tile: chunk ^= (row&7)
#define SWZ(b) ((b) ^ (((b) >> 3) & 0x70))

// ============================ convert fp32 -> fp16 ============================
__global__ void convert_fp16_kernel(const float* __restrict__ x,
                                    const float* __restrict__ W) {
    size_t i = (size_t)blockIdx.x * blockDim.x + threadIdx.x;
    const size_t n1 = (size_t)BB * HH / 4;
    const size_t n2 = (size_t)VV * HH / 4;
    if (i < n1) {
        float4 v = reinterpret_cast<const float4*>(x)[i];
        __half2* o = reinterpret_cast<__half2*>(g_xb);
        o[2*i]   = __floats2half2_rn(v.x, v.y);
        o[2*i+1] = __floats2half2_rn(v.z, v.w);
    } else if (i < n1 + n2) {
        size_t j = i - n1;
        float4 v = reinterpret_cast<const float4*>(W)[j];
        __half2* o = reinterpret_cast<__half2*>(g_wb);
        o[2*j]   = __floats2half2_rn(v.x, v.y);
        o[2*j+1] = __floats2half2_rn(v.z, v.w);
    }
}

// ============== exact fp32 gather of logit[y_r] (one warp per row) ===========
// y is INT32 (JAX x64-disabled: randint(dtype=int64) silently yields int32).
__global__ void gather_target_kernel(const float* __restrict__ x,
                                     const float* __restrict__ W,
                                     const int* __restrict__ y) {
    int r = blockIdx.x * 8 + (threadIdx.x >> 5);
    int l = threadIdx.x & 31;
    if (r >= BB/2) return;
    int yy = y[r];
    if (yy == IGNORE_INDEX || yy < 0 || yy >= VV) { if (l == 0) g_L[r] = 0.f; return; }
    const float4* xr = reinterpret_cast<const float4*>(x + (size_t)r * HH);
    const float4* wr = reinterpret_cast<const float4*>(W + (size_t)yy * HH);
    float s = 0.f;
    #pragma unroll 4
    for (int i = l; i < HH/4; i += 32) {
        float4 a = xr[i], b = wr[i];
        s += a.x*b.x + a.y*b.y + a.z*b.z + a.w*b.w;
    }
    #pragma unroll
    for (int o = 16; o; o >>= 1) s += __shfl_xor_sync(0xffffffffu, s, o);
    if (l == 0) g_L[r] = s;
}

// ============================ fused GEMM + reductions ========================
__global__ void __launch_bounds__(256, 2)
orpo_gemm_kernel() {
    extern __shared__ unsigned char smem_raw[];
    unsigned char* Asm = smem_raw;                 // 2 stages * 16384 B
    unsigned char* Bsm = smem_raw + 2 * 16384;     // 2 stages * 16384 B
    __shared__ float Ssh[2][TM];
    __shared__ float Tsh[2][TM];

    const int tid = threadIdx.x;
    const int l   = tid & 31;
    const int wid = tid >> 5;
    const int wm  = wid & 3;       // 4 warps in M (32 rows each)
    const int wn  = wid >> 2;      // 2 warps in N (64 cols each)
    const int rowBase = blockIdx.x * TM;

    if (tid < TM) {
        Ssh[0][tid] = 0.f; Ssh[1][tid] = 0.f;
        Tsh[0][tid] = 0.f; Tsh[1][tid] = 0.f;
    }
    __syncthreads();

    const uint32_t aBase = (uint32_t)__cvta_generic_to_shared(Asm);
    const uint32_t bBase = (uint32_t)__cvta_generic_to_shared(Bsm);

    // cp.async addressing: thread covers (r0 + it*32, ch) for it=0..3
    const int r0 = tid >> 3;
    const int ch = tid & 7;
    const uint32_t dOff0 = SWZ((uint32_t)(r0 * 128 + ch * 16)); // + it*4096 (r&7 invariant)
    const __half* gaP = g_xb + (size_t)(rowBase + r0) * HH + ch * 8;

    // ldmatrix per-lane constants
    const uint32_t aColB = (uint32_t)((l >> 4) << 4);        // A k-offset bytes
    const uint32_t bColB = (uint32_t)(((l >> 3) & 1) << 4);  // B k-offset bytes

    float acc[2][8][4];

    for (int t = blockIdx.y; t < NTILES; t += NVC) {
        #pragma unroll
        for (int mt = 0; mt < 2; ++mt)
            #pragma unroll
            for (int nt = 0; nt < 8; ++nt)
                #pragma unroll
                for (int e = 0; e < 4; ++e) acc[mt][nt][e] = 0.f;

        const __half* gbP = g_wb + (size_t)(t * TN + r0) * HH + ch * 8;

        // prologue: stage 0
        #pragma unroll
        for (int it = 0; it < 4; ++it) {
            uint32_t da = aBase + dOff0 + it * 4096;
            const void* ga = gaP + (size_t)it * 32 * HH;
            asm volatile("cp.async.cg.shared.global [%0], [%1], 16;\n" :: "r"(da), "l"(ga));
            uint32_t db = bBase + dOff0 + it * 4096;
            const void* gb = gbP + (size_t)it * 32 * HH;
            asm volatile("cp.async.cg.shared.global [%0], [%1], 16;\n" :: "r"(db), "l"(gb));
        }
        asm volatile("cp.async.commit_group;\n" ::: "memory");

        for (int kt = 0; kt < NKT; ++kt) {
            const int cur = kt & 1;
            if (kt + 1 < NKT) {
                const int s = cur ^ 1;
                const int kof = (kt + 1) * TK;   // elements
                #pragma unroll
                for (int it = 0; it < 4; ++it) {
                    uint32_t da = aBase + s * 16384 + dOff0 + it * 4096;
                    const void* ga = gaP + (size_t)it * 32 * HH + kof;
                    asm volatile("cp.async.cg.shared.global [%0], [%1], 16;\n" :: "r"(da), "l"(ga));
                    uint32_t db = bBase + s * 16384 + dOff0 + it * 4096;
                    const void* gb = gbP + (size_t)it * 32 * HH + kof;
                    asm volatile("cp.async.cg.shared.global [%0], [%1], 16;\n" :: "r"(db), "l"(gb));
                }
                asm volatile("cp.async.commit_group;\n" ::: "memory");
                asm volatile("cp.async.wait_group 1;\n" ::: "memory");
            } else {
                asm volatile("cp.async.wait_group 0;\n" ::: "memory");
            }
            __syncthreads();

            const uint32_t aS = aBase + cur * 16384;
            const uint32_t bS = bBase + cur * 16384;
            #pragma unroll
            for (int kk = 0; kk < 4; ++kk) {   // 4 x k16 per stage
                uint32_t af[2][4];
                #pragma unroll
                for (int mt = 0; mt < 2; ++mt) {
                    uint32_t off = (uint32_t)((wm * 32 + mt * 16 + (l & 15)) * 128 + kk * 32) + aColB;
                    uint32_t ad = aS + SWZ(off);
                    asm volatile("ldmatrix.sync.aligned.m8n8.x4.shared.b16 {%0,%1,%2,%3}, [%4];\n"
                        : "=r"(af[mt][0]), "=r"(af[mt][1]), "=r"(af[mt][2]), "=r"(af[mt][3])
                        : "r"(ad));
                }
                uint32_t bf[8][2];
                #pragma unroll
                for (int np = 0; np < 4; ++np) {
                    uint32_t off = (uint32_t)((wn * 64 + np * 16 + ((l >> 4) << 3) + (l & 7)) * 128 + kk * 32) + bColB;
                    uint32_t bd = bS + SWZ(off);
                    asm volatile("ldmatrix.sync.aligned.m8n8.x4.shared.b16 {%0,%1,%2,%3}, [%4];\n"
                        : "=r"(bf[2*np][0]), "=r"(bf[2*np][1]), "=r"(bf[2*np+1][0]), "=r"(bf[2*np+1][1])
                        : "r"(bd));
                }
                #pragma unroll
                for (int mt = 0; mt < 2; ++mt)
                    #pragma unroll
                    for (int nt = 0; nt < 8; ++nt) {
                        asm volatile(
                            "mma.sync.aligned.m16n8k16.row.col.f32.f16.f16.f32 "
                            "{%0,%1,%2,%3}, {%4,%5,%6,%7}, {%8,%9}, {%0,%1,%2,%3};\n"
                            : "+f"(acc[mt][nt][0]), "+f"(acc[mt][nt][1]),
                              "+f"(acc[mt][nt][2]), "+f"(acc[mt][nt][3])
                            : "r"(af[mt][0]), "r"(af[mt][1]), "r"(af[mt][2]), "r"(af[mt][3]),
                              "r"(bf[nt][0]), "r"(bf[nt][1]));
                    }
            }
            __syncthreads();
        }

        // ---- epilogue: online reductions (no logits stored) ----
        float sE[4] = {0.f, 0.f, 0.f, 0.f};
        float sTt[4] = {0.f, 0.f, 0.f, 0.f};
        #pragma unroll
        for (int mt = 0; mt < 2; ++mt)
            #pragma unroll
            for (int nt = 0; nt < 8; ++nt)
                #pragma unroll
                for (int e = 0; e < 4; ++e) {
                    float v = acc[mt][nt][e];
                    int rp = mt * 2 + (e >> 1);
                    sE[rp]  += __expf(v);
                    sTt[rp] += v;
                }
        #pragma unroll
        for (int ofs = 1; ofs <= 2; ofs <<= 1)
            #pragma unroll
            for (int rp = 0; rp < 4; ++rp) {
                sE[rp]  += __shfl_xor_sync(0xffffffffu, sE[rp], ofs);
                sTt[rp] += __shfl_xor_sync(0xffffffffu, sTt[rp], ofs);
            }
        if ((l & 3) == 0) {
            #pragma unroll
            for (int rp = 0; rp < 4; ++rp) {
                int rl = wm * 32 + (rp >> 1) * 16 + ((rp & 1) << 3) + (l >> 2);
                Ssh[wn][rl] += sE[rp];     // unique (wn,rl) writer -> no atomics
                Tsh[wn][rl] += sTt[rp];
            }
        }
    }

    __syncthreads();
    if (tid < TM) {
        g_S[blockIdx.y * BB + rowBase + tid] = Ssh[0][tid] + Ssh[1][tid];
        g_T[blockIdx.y * BB + rowBase + tid] = Tsh[0][tid] + Tsh[1][tid];
    }
}

// ================= finalize stage 1: one ORPO pair per thread =================
__global__ void __launch_bounds__(256)
orpo_finalize1_kernel(const int* __restrict__ y) {
    __shared__ double red[256];
    const int tid = threadIdx.x;
    const int r = blockIdx.x * 256 + tid;        // pair index, 0..2047

    // row r (chosen) and r + BB/2 (rejected)
    double S0 = 0.0, T0 = 0.0, S1 = 0.0, T1 = 0.0;
    #pragma unroll
    for (int c = 0; c < NVC; ++c) {
        S0 += (double)g_S[c*BB + r];
        T0 += (double)g_T[c*BB + r];
        S1 += (double)g_S[c*BB + r + BB/2];
        T1 += (double)g_T[c*BB + r + BB/2];
    }
    double lz0 = log(S0);
    double chs = T0 / (double)VV - lz0;
    double rj  = T1 / (double)VV - log(S1);

    double pnll = 0.0, pcnt = 0.0;
    if (y[r] != IGNORE_INDEX) { pnll = lz0 - (double)g_L[r]; pcnt = 1.0; }

    double lo = (chs - rj) - (log1p(-exp(chs)) - log1p(-exp(rj)));
    double ls = (lo > 0.0) ? -log1p(exp(-lo)) : lo - log1p(exp(lo));
    double por = 0.1 * ls;                        // BETA * log_sigmoid(log_odds)

    red[tid] = pnll; __syncthreads();
    for (int s = 128; s > 0; s >>= 1) { if (tid < s) red[tid] += red[tid + s]; __syncthreads(); }
    if (tid == 0) g_pnll[blockIdx.x] = red[0];
    __syncthreads();
    red[tid] = pcnt; __syncthreads();
    for (int s = 128; s > 0; s >>= 1) { if (tid < s) red[tid] += red[tid + s]; __syncthreads(); }
    if (tid == 0) g_pcnt[blockIdx.x] = red[0];
    __syncthreads();
    red[tid] = por; __syncthreads();
    for (int s = 128; s > 0; s >>= 1) { if (tid < s) red[tid] += red[tid + s]; __syncthreads(); }
    if (tid == 0) g_por[blockIdx.x] = red[0];
}

// ================= finalize stage 2: deterministic 8-way sum =================
__global__ void orpo_finalize2_kernel(float* __restrict__ out) {
    if (threadIdx.x == 0) {
        double nll = 0.0, cnt = 0.0, por = 0.0;
        #pragma unroll
        for (int b = 0; b < FIN_BLOCKS; ++b) {   // fixed order -> deterministic
            nll += g_pnll[b]; cnt += g_pcnt[b]; por += g_por[b];
        }
        double denom = (cnt > 1.0) ? cnt : 1.0;
        out[0] = (float)(nll / denom - por / (double)(BB/2));
    }
}

// ============================ launch =========================================
extern "C" void kernel_launch(void* const* d_in, const int* in_sizes, int n_in,
                              void* d_out, int out_size) {
    const float* x = (const float*)d_in[0];
    const float* W = (const float*)d_in[1];
    const int* y = (const int*)d_in[2];     // int32 labels
    float* out = (float*)d_out;

    const size_t nvec = ((size_t)BB*HH + (size_t)VV*HH) / 4;
    convert_fp16_kernel<<<(int)((nvec + 255) / 256), 256>>>(x, W);

    gather_target_kernel<<<(BB/2 + 7) / 8, 256>>>(x, W, y);

    cudaFuncSetAttribute(orpo_gemm_kernel,
                         cudaFuncAttributeMaxDynamicSharedMemorySize, 65536);
    dim3 grid(BB / TM, NVC);
    orpo_gemm_kernel<<<grid, 256, 65536>>>();

    orpo_finalize1_kernel<<<FIN_BLOCKS, 256>>>(y);
    orpo_finalize2_kernel<<<1, 32>>>(out);
}